// round 3
// baseline (speedup 1.0000x reference)
#include <cuda_runtime.h>
#include <cuda_bf16.h>
#include <cstdint>

// Problem constants (GCNConv_68771016344004): N=100000, F_IN=128, F_OUT=32, E=N*16
#define F_IN   128
#define F_OUT  32
#define MAX_N  100000

// Scratch for Xp = X*W + b  (12.8 MB) — __device__ global per allocation rules.
__device__ float g_Xp[MAX_N * F_OUT];

// ---------------- packed fp32x2 helpers (sm_103a FFMA2) ----------------
__device__ __forceinline__ uint64_t pack2(float x, float y) {
    uint64_t r;
    asm("mov.b64 %0, {%1, %2};" : "=l"(r) : "f"(x), "f"(y));
    return r;
}
__device__ __forceinline__ void unpack2(uint64_t v, float& x, float& y) {
    asm("mov.b64 {%0, %1}, %2;" : "=f"(x), "=f"(y) : "l"(v));
}
__device__ __forceinline__ void ffma2(uint64_t& d, uint64_t a, uint64_t b) {
    asm("fma.rn.f32x2 %0, %1, %2, %0;" : "+l"(d) : "l"(a), "l"(b));
}

// ---------------- Kernel 1: Xp = X @ W + b -----------------------------
// Block: 128 threads (4 warps), tile = 64 rows.
// Shared: Ws [128][32] = 16KB, Xs transposed [k][row] [128][64] = 32KB (48KB total).
// Warp w owns output cols [8w, 8w+8); lane owns rows {lane, lane+32} of the tile.
// W reads are warp-broadcast LDS.64; X reads conflict-free via XOR swizzle.
__global__ __launch_bounds__(128) void gemm_bias_kernel(
    const float* __restrict__ X, const float* __restrict__ W,
    const float* __restrict__ b, int n)
{
    __shared__ float Ws[F_IN][F_OUT];       // [k][j]
    __shared__ float Xs[F_IN][64];          // [k][row], col XOR-swizzled by (k&31)

    const int tid  = threadIdx.x;
    const int lane = tid & 31;
    const int w    = tid >> 5;              // warp id 0..3
    const int row0 = blockIdx.x * 64;
    const int nrows = min(64, n - row0);

    // Load W into shared (float4, coalesced)
    {
        const float4* W4 = reinterpret_cast<const float4*>(W);
        float4* Ws4 = reinterpret_cast<float4*>(&Ws[0][0]);
        #pragma unroll
        for (int i = tid; i < (F_IN * F_OUT) / 4; i += 128) Ws4[i] = W4[i];
    }

    // Load X tile, transposed into Xs[k][row] with XOR swizzle on the row index.
    // idx: r = idx>>5 (tile row), kq = idx&31 (float4 index along k)
    for (int idx = tid; idx < 64 * 32; idx += 128) {
        const int r  = idx >> 5;
        const int kq = idx & 31;
        float4 v = make_float4(0.f, 0.f, 0.f, 0.f);
        if (r < nrows)
            v = reinterpret_cast<const float4*>(X + (size_t)(row0 + r) * F_IN)[kq];
        const int k0 = kq * 4;
        Xs[k0 + 0][r ^ ((k0 + 0) & 31)] = v.x;
        Xs[k0 + 1][r ^ ((k0 + 1) & 31)] = v.y;
        Xs[k0 + 2][r ^ ((k0 + 2) & 31)] = v.z;
        Xs[k0 + 3][r ^ ((k0 + 3) & 31)] = v.w;
    }
    __syncthreads();

    // Accumulators: 2 rows x 8 cols as 2x4 packed f32x2
    uint64_t acc[2][4];
    #pragma unroll
    for (int i = 0; i < 2; i++)
        #pragma unroll
        for (int j = 0; j < 4; j++) acc[i][j] = 0ull;

    #pragma unroll 4
    for (int k = 0; k < F_IN; k++) {
        const int sw = lane ^ (k & 31);
        const float x0 = Xs[k][sw];
        const float x1 = Xs[k][32 + sw];
        const uint64_t xa0 = pack2(x0, x0);
        const uint64_t xa1 = pack2(x1, x1);
        const uint64_t* wrow = reinterpret_cast<const uint64_t*>(&Ws[k][w * 8]);
        #pragma unroll
        for (int j = 0; j < 4; j++) {
            const uint64_t wv = wrow[j];   // warp-uniform broadcast LDS.64
            ffma2(acc[0][j], xa0, wv);
            ffma2(acc[1][j], xa1, wv);
        }
    }

    // Bias (warp-uniform loads, cached)
    float bj[8];
    #pragma unroll
    for (int j = 0; j < 8; j++) bj[j] = __ldg(&b[w * 8 + j]);

    #pragma unroll
    for (int i = 0; i < 2; i++) {
        const int r = lane + 32 * i;
        if (r < nrows) {
            float* out = g_Xp + (size_t)(row0 + r) * F_OUT + w * 8;
            #pragma unroll
            for (int j = 0; j < 4; j++) {
                float lo, hi;
                unpack2(acc[i][j], lo, hi);
                out[2 * j + 0] = lo + bj[2 * j + 0];
                out[2 * j + 1] = hi + bj[2 * j + 1];
            }
        }
    }
}

// ---------------- Kernel 2: out[i] = sum_e deg[e] * Xp[col[e]] ----------
// One warp per node; lane = output column. Gathers are 128B coalesced rows
// of Xp (L2-resident). 4 accumulators for MLP.
__global__ __launch_bounds__(256) void spmm_kernel(
    const int* __restrict__ rp, const int* __restrict__ ci,
    const float* __restrict__ deg, float* __restrict__ out, int n)
{
    const int gwarp = (blockIdx.x * blockDim.x + threadIdx.x) >> 5;
    const int lane  = threadIdx.x & 31;
    if (gwarp >= n) return;

    const int start = rp[gwarp];
    const int end   = rp[gwarp + 1];

    float a0 = 0.f, a1 = 0.f, a2 = 0.f, a3 = 0.f;

    for (int s = start; s < end; s += 32) {
        const int e = s + lane;
        int   c = 0;
        float d = 0.f;
        if (e < end) { c = ci[e]; d = deg[e]; }
        const int m = min(32, end - s);

        int t = 0;
        for (; t + 4 <= m; t += 4) {
            const int   c0 = __shfl_sync(0xffffffffu, c, t + 0);
            const int   c1 = __shfl_sync(0xffffffffu, c, t + 1);
            const int   c2 = __shfl_sync(0xffffffffu, c, t + 2);
            const int   c3 = __shfl_sync(0xffffffffu, c, t + 3);
            const float d0 = __shfl_sync(0xffffffffu, d, t + 0);
            const float d1 = __shfl_sync(0xffffffffu, d, t + 1);
            const float d2 = __shfl_sync(0xffffffffu, d, t + 2);
            const float d3 = __shfl_sync(0xffffffffu, d, t + 3);
            a0 += d0 * g_Xp[c0 * F_OUT + lane];
            a1 += d1 * g_Xp[c1 * F_OUT + lane];
            a2 += d2 * g_Xp[c2 * F_OUT + lane];
            a3 += d3 * g_Xp[c3 * F_OUT + lane];
        }
        for (; t < m; ++t) {
            const int   cc = __shfl_sync(0xffffffffu, c, t);
            const float dd = __shfl_sync(0xffffffffu, d, t);
            a0 += dd * g_Xp[cc * F_OUT + lane];
        }
    }

    out[(size_t)gwarp * F_OUT + lane] = (a0 + a1) + (a2 + a3);
}

// ---------------- launch -----------------------------------------------
extern "C" void kernel_launch(void* const* d_in, const int* in_sizes, int n_in,
                              void* d_out, int out_size)
{
    const float* X   = (const float*)d_in[0];   // [N,128]
    const float* W   = (const float*)d_in[1];   // [128,32]
    const float* b   = (const float*)d_in[2];   // [32]
    const int*   rp  = (const int*)  d_in[3];   // [N+1]
    const int*   ci  = (const int*)  d_in[4];   // [E]
    const float* deg = (const float*)d_in[5];   // [E]
    float* out = (float*)d_out;                 // [N,32]

    const int n = in_sizes[0] / F_IN;

    gemm_bias_kernel<<<(n + 63) / 64, 128>>>(X, W, b, n);
    spmm_kernel<<<(n + 7) / 8, 256>>>(rp, ci, deg, out, n);
}

// round 5
// speedup vs baseline: 1.2381x; 1.2381x over previous
#include <cuda_runtime.h>
#include <cuda_bf16.h>
#include <cstdint>

// Problem constants (GCNConv_68771016344004): N=100000, F_IN=128, F_OUT=32, E=N*16
#define F_IN   128
#define F_OUT  32
#define MAX_N  100000

// Scratch for Xp = X*W + b  (12.8 MB) — __device__ global per allocation rules.
__device__ float g_Xp[MAX_N * F_OUT];

// ---------------- packed fp32x2 helpers (sm_103a FFMA2) ----------------
__device__ __forceinline__ uint64_t pack2(float x, float y) {
    uint64_t r;
    asm("mov.b64 %0, {%1, %2};" : "=l"(r) : "f"(x), "f"(y));
    return r;
}
__device__ __forceinline__ void unpack2(uint64_t v, float& x, float& y) {
    asm("mov.b64 {%0, %1}, %2;" : "=f"(x), "=f"(y) : "l"(v));
}
__device__ __forceinline__ void ffma2(uint64_t& d, uint64_t a, uint64_t b) {
    asm("fma.rn.f32x2 %0, %1, %2, %0;" : "+l"(d) : "l"(a), "l"(b));
}

// ---------------- Kernel 1: Xp = X @ W + b -----------------------------
// Thread-per-row. X streamed via LDG.128 into registers (no smem transpose,
// no mainloop barriers). W in shared, read as warp-uniform LDS.128
// (broadcast = conflict-free, half the issue slots of LDS.64).
// Accumulators: 32 cols as 16 packed f32x2.
__global__ __launch_bounds__(128) void gemm_bias_kernel(
    const float* __restrict__ X, const float* __restrict__ W,
    const float* __restrict__ b, int n)
{
    __shared__ __align__(16) float Ws[F_IN * F_OUT];   // [k][j], 16KB

    const int tid = threadIdx.x;
    {
        const float4* W4 = reinterpret_cast<const float4*>(W);
        float4* Ws4 = reinterpret_cast<float4*>(Ws);
        #pragma unroll
        for (int i = tid; i < (F_IN * F_OUT) / 4; i += 128) Ws4[i] = W4[i];
    }
    __syncthreads();

    const int row = blockIdx.x * 128 + tid;
    if (row >= n) return;

    const float4* Xrow = reinterpret_cast<const float4*>(X + (size_t)row * F_IN);

    uint64_t acc[16];
    #pragma unroll
    for (int j = 0; j < 16; j++) acc[j] = 0ull;

    #pragma unroll 2
    for (int kq = 0; kq < F_IN / 4; kq++) {
        const float4 xv = __ldg(&Xrow[kq]);
        const float xk[4] = {xv.x, xv.y, xv.z, xv.w};
        #pragma unroll
        for (int kk = 0; kk < 4; kk++) {
            const uint64_t xd = pack2(xk[kk], xk[kk]);
            const int k = kq * 4 + kk;
            const ulonglong2* Wk = reinterpret_cast<const ulonglong2*>(Ws + k * F_OUT);
            #pragma unroll
            for (int j4 = 0; j4 < 8; j4++) {
                const ulonglong2 wq = Wk[j4];     // LDS.128, warp-uniform broadcast
                ffma2(acc[2 * j4 + 0], xd, wq.x);
                ffma2(acc[2 * j4 + 1], xd, wq.y);
            }
        }
    }

    float* out = g_Xp + (size_t)row * F_OUT;
    const float4* b4 = reinterpret_cast<const float4*>(b);
    #pragma unroll
    for (int j4 = 0; j4 < 8; j4++) {
        const float4 bv = __ldg(&b4[j4]);
        float l0, h0, l1, h1;
        unpack2(acc[2 * j4 + 0], l0, h0);
        unpack2(acc[2 * j4 + 1], l1, h1);
        reinterpret_cast<float4*>(out)[j4] =
            make_float4(l0 + bv.x, h0 + bv.y, l1 + bv.z, h1 + bv.w);
    }
}

// ---------------- Kernel 2: out[i] = sum_e deg[e] * Xp[col[e]] ----------
// Warp per node. Lanes split into 4 groups of 8: group g gathers edge
// (4t+g)'s full 32-float Xp row as 8 x LDG.128 (one float4 per lane).
// Each warp-instruction moves 4 rows (512B) with 4-deep MLP. Cross-group
// combine via 2-stage shfl_xor; lanes 0-7 emit one coalesced STG.128 row.
__global__ __launch_bounds__(256) void spmm_kernel(
    const int* __restrict__ rp, const int* __restrict__ ci,
    const float* __restrict__ deg, float* __restrict__ out, int n)
{
    const int node = (blockIdx.x * 256 + threadIdx.x) >> 5;
    if (node >= n) return;
    const int lane = threadIdx.x & 31;
    const int g = lane >> 3;          // edge sub-group 0..3
    const int q = lane & 7;           // float4 chunk within row

    const int start = rp[node];
    const int end   = rp[node + 1];
    const int m_all = end - start;

    const float4* Xp4 = reinterpret_cast<const float4*>(g_Xp);

    float4 a0 = make_float4(0.f, 0.f, 0.f, 0.f);
    float4 a1 = make_float4(0.f, 0.f, 0.f, 0.f);

    if (m_all == 16) {
        // Fast path: uniform degree 16 -> 4 fully unrolled group-iterations.
        int   c = 0; float d = 0.f;
        if (lane < 16) { c = ci[start + lane]; d = deg[start + lane]; }
        #pragma unroll
        for (int t = 0; t < 4; ++t) {
            const int   cg = __shfl_sync(0xffffffffu, c, t * 4 + g);
            const float dg = __shfl_sync(0xffffffffu, d, t * 4 + g);
            const float4 v = __ldg(&Xp4[(size_t)cg * 8 + q]);
            float4& a = (t & 1) ? a1 : a0;
            a.x = fmaf(dg, v.x, a.x);
            a.y = fmaf(dg, v.y, a.y);
            a.z = fmaf(dg, v.z, a.z);
            a.w = fmaf(dg, v.w, a.w);
        }
    } else {
        // Generic path: any degree.
        for (int s = start; s < end; s += 32) {
            const int m = min(32, end - s);
            int   c = 0; float d = 0.f;
            if (lane < m) { c = ci[s + lane]; d = deg[s + lane]; }
            const int tmax = (m + 3) >> 2;
            for (int t = 0; t < tmax; ++t) {
                const int   idx = t * 4 + g;
                const int   cg = __shfl_sync(0xffffffffu, c, idx);
                const float dg = __shfl_sync(0xffffffffu, d, idx);
                if (idx < m) {
                    const float4 v = __ldg(&Xp4[(size_t)cg * 8 + q]);
                    a0.x = fmaf(dg, v.x, a0.x);
                    a0.y = fmaf(dg, v.y, a0.y);
                    a0.z = fmaf(dg, v.z, a0.z);
                    a0.w = fmaf(dg, v.w, a0.w);
                }
            }
        }
    }

    a0.x += a1.x; a0.y += a1.y; a0.z += a1.z; a0.w += a1.w;

    // Reduce across the 4 groups (lanes xor 8, xor 16)
    #pragma unroll
    for (int off = 8; off <= 16; off <<= 1) {
        a0.x += __shfl_xor_sync(0xffffffffu, a0.x, off);
        a0.y += __shfl_xor_sync(0xffffffffu, a0.y, off);
        a0.z += __shfl_xor_sync(0xffffffffu, a0.z, off);
        a0.w += __shfl_xor_sync(0xffffffffu, a0.w, off);
    }

    if (lane < 8)
        reinterpret_cast<float4*>(out + (size_t)node * F_OUT)[q] = a0;
}

// ---------------- launch -----------------------------------------------
extern "C" void kernel_launch(void* const* d_in, const int* in_sizes, int n_in,
                              void* d_out, int out_size)
{
    const float* X   = (const float*)d_in[0];   // [N,128]
    const float* W   = (const float*)d_in[1];   // [128,32]
    const float* b   = (const float*)d_in[2];   // [32]
    const int*   rp  = (const int*)  d_in[3];   // [N+1]
    const int*   ci  = (const int*)  d_in[4];   // [E]
    const float* deg = (const float*)d_in[5];   // [E]
    float* out = (float*)d_out;                 // [N,32]

    const int n = in_sizes[0] / F_IN;

    gemm_bias_kernel<<<(n + 127) / 128, 128>>>(X, W, b, n);
    spmm_kernel<<<(n + 7) / 8, 256>>>(rp, ci, deg, out, n);
}

// round 6
// speedup vs baseline: 2.0434x; 1.6505x over previous
#include <cuda_runtime.h>
#include <cuda_bf16.h>
#include <cstdint>

// Problem constants (GCNConv_68771016344004): N=100000, F_IN=128, F_OUT=32, E=N*16
#define F_IN   128
#define F_OUT  32
#define MAX_N  100000

// Scratch for Xp = X*W + b  (12.8 MB) — __device__ global per allocation rules.
__device__ float g_Xp[MAX_N * F_OUT];

// ---------------- helpers ----------------
__device__ __forceinline__ uint32_t pack_bf16x2(float a, float b) {
    // (a -> low half, b -> high half)
    __nv_bfloat162 h = __floats2bfloat162_rn(a, b);
    return *reinterpret_cast<uint32_t*>(&h);
}

__device__ __forceinline__ void ldmatrix_x4(uint32_t r[4], uint32_t addr) {
    asm volatile("ldmatrix.sync.aligned.m8n8.x4.shared.b16 {%0,%1,%2,%3}, [%4];"
                 : "=r"(r[0]), "=r"(r[1]), "=r"(r[2]), "=r"(r[3]) : "r"(addr));
}
__device__ __forceinline__ void ldmatrix_x4_trans(uint32_t r[4], uint32_t addr) {
    asm volatile("ldmatrix.sync.aligned.m8n8.x4.trans.shared.b16 {%0,%1,%2,%3}, [%4];"
                 : "=r"(r[0]), "=r"(r[1]), "=r"(r[2]), "=r"(r[3]) : "r"(addr));
}
__device__ __forceinline__ void mma_bf16(float c[4], const uint32_t a[4],
                                         uint32_t b0, uint32_t b1) {
    asm volatile(
        "mma.sync.aligned.m16n8k16.row.col.f32.bf16.bf16.f32 "
        "{%0,%1,%2,%3}, {%4,%5,%6,%7}, {%8,%9}, {%0,%1,%2,%3};"
        : "+f"(c[0]), "+f"(c[1]), "+f"(c[2]), "+f"(c[3])
        : "r"(a[0]), "r"(a[1]), "r"(a[2]), "r"(a[3]), "r"(b0), "r"(b1));
}

// ---------------- Kernel 1: Xp = X @ W + b  (bf16-split tensor-core) ----
// CTA: 256 threads (8 warps), tile = 128 rows. K=128 done in 2 halves of 64
// so the split-bf16 tiles fit in <48KB static smem.
//   out = Xhi*Whi + Xhi*Wlo + Xlo*Whi   (lo*lo dropped, ~2^-18 rel)
// A tiles padded to 72 cols (row stride 144B -> ldmatrix banks advance by 4,
// conflict-free); B tiles padded to 40 cols (80B stride, gcd(20,32)=4 -> 8
// distinct banks per 8-row ldmatrix group).
#define APAD 72
#define BPAD 40

__global__ __launch_bounds__(256) void gemm_mma_kernel(
    const float* __restrict__ X, const float* __restrict__ W,
    const float* __restrict__ b, int n)
{
    __shared__ __align__(16) __nv_bfloat16 Ahi[128][APAD];
    __shared__ __align__(16) __nv_bfloat16 Alo[128][APAD];
    __shared__ __align__(16) __nv_bfloat16 Bhi[64][BPAD];
    __shared__ __align__(16) __nv_bfloat16 Blo[64][BPAD];

    const int tid  = threadIdx.x;
    const int lane = tid & 31;
    const int w    = tid >> 5;              // warp 0..7, owns rows [16w,16w+16)
    const int row0 = blockIdx.x * 128;

    float acc[4][4];                        // 4 n8-blocks x 4
    #pragma unroll
    for (int nb = 0; nb < 4; nb++)
        #pragma unroll
        for (int j = 0; j < 4; j++) acc[nb][j] = 0.f;

    #pragma unroll
    for (int kh = 0; kh < 2; kh++) {
        __syncthreads();   // previous half's tiles fully consumed

        // ---- load + split A half: 128 rows x 64 k (2048 float4, 8/thread)
        #pragma unroll
        for (int i = 0; i < 8; i++) {
            const int idx = tid + 256 * i;
            const int r   = idx >> 4;       // 16 float4 per row-half
            const int q   = idx & 15;
            float4 v = make_float4(0.f, 0.f, 0.f, 0.f);
            if (row0 + r < n)
                v = __ldg(reinterpret_cast<const float4*>(
                        X + (size_t)(row0 + r) * F_IN + kh * 64) + q);
            float hx = __bfloat162float(__float2bfloat16_rn(v.x));
            float hy = __bfloat162float(__float2bfloat16_rn(v.y));
            float hz = __bfloat162float(__float2bfloat16_rn(v.z));
            float hw = __bfloat162float(__float2bfloat16_rn(v.w));
            uint2 hi = make_uint2(pack_bf16x2(hx, hy), pack_bf16x2(hz, hw));
            uint2 lo = make_uint2(pack_bf16x2(v.x - hx, v.y - hy),
                                  pack_bf16x2(v.z - hz, v.w - hw));
            *reinterpret_cast<uint2*>(&Ahi[r][q * 4]) = hi;
            *reinterpret_cast<uint2*>(&Alo[r][q * 4]) = lo;
        }
        // ---- load + split B half: 64 k-rows x 32 cols (512 float4, 2/thread)
        #pragma unroll
        for (int i = 0; i < 2; i++) {
            const int idx = tid + 256 * i;
            const int r   = idx >> 3;       // 8 float4 per W row
            const int q   = idx & 7;
            const float4 v = __ldg(reinterpret_cast<const float4*>(
                    W + (size_t)(kh * 64 + r) * F_OUT) + q);
            float hx = __bfloat162float(__float2bfloat16_rn(v.x));
            float hy = __bfloat162float(__float2bfloat16_rn(v.y));
            float hz = __bfloat162float(__float2bfloat16_rn(v.z));
            float hw = __bfloat162float(__float2bfloat16_rn(v.w));
            uint2 hi = make_uint2(pack_bf16x2(hx, hy), pack_bf16x2(hz, hw));
            uint2 lo = make_uint2(pack_bf16x2(v.x - hx, v.y - hy),
                                  pack_bf16x2(v.z - hz, v.w - hw));
            *reinterpret_cast<uint2*>(&Bhi[r][q * 4]) = hi;
            *reinterpret_cast<uint2*>(&Blo[r][q * 4]) = lo;
        }
        __syncthreads();

        // ---- 4 k16-chunks per half
        #pragma unroll
        for (int kc = 0; kc < 4; kc++) {
            uint32_t ahi[4], alo[4];
            {
                const int ar = 16 * w + (lane & 15);
                const int ac = kc * 16 + (lane >> 4) * 8;
                ldmatrix_x4(ahi, (uint32_t)__cvta_generic_to_shared(&Ahi[ar][ac]));
                ldmatrix_x4(alo, (uint32_t)__cvta_generic_to_shared(&Alo[ar][ac]));
            }
            uint32_t bhi[8], blo[8];        // [n0-15 | n16-31], each {k0-7,k8-15} pairs
            {
                const int br = kc * 16 + (lane & 15);
                const int bc0 = (lane >> 4) * 8;
                ldmatrix_x4_trans(bhi,     (uint32_t)__cvta_generic_to_shared(&Bhi[br][bc0]));
                ldmatrix_x4_trans(bhi + 4, (uint32_t)__cvta_generic_to_shared(&Bhi[br][16 + bc0]));
                ldmatrix_x4_trans(blo,     (uint32_t)__cvta_generic_to_shared(&Blo[br][bc0]));
                ldmatrix_x4_trans(blo + 4, (uint32_t)__cvta_generic_to_shared(&Blo[br][16 + bc0]));
            }
            #pragma unroll
            for (int nb = 0; nb < 4; nb++) {
                const int o = (nb >> 1) * 4 + (nb & 1) * 2;   // reg pair offset
                mma_bf16(acc[nb], ahi, bhi[o], bhi[o + 1]);   // hi*hi
                mma_bf16(acc[nb], ahi, blo[o], blo[o + 1]);   // hi*lo
                mma_bf16(acc[nb], alo, bhi[o], bhi[o + 1]);   // lo*hi
            }
        }
    }

    // ---- epilogue: + bias, store fp32 rows of Xp
    const int r0 = row0 + 16 * w + (lane >> 2);
    const int c0 = (lane & 3) * 2;
    #pragma unroll
    for (int nb = 0; nb < 4; nb++) {
        const int col = nb * 8 + c0;
        const float2 bv = __ldg(reinterpret_cast<const float2*>(b + col));
        if (r0 < n)
            *reinterpret_cast<float2*>(g_Xp + (size_t)r0 * F_OUT + col) =
                make_float2(acc[nb][0] + bv.x, acc[nb][1] + bv.y);
        if (r0 + 8 < n)
            *reinterpret_cast<float2*>(g_Xp + (size_t)(r0 + 8) * F_OUT + col) =
                make_float2(acc[nb][2] + bv.x, acc[nb][3] + bv.y);
    }
}

// ---------------- Kernel 2: out[i] = sum_e deg[e] * Xp[col[e]] ----------
// (unchanged from R4 — warp/node, 4x8 lane groups, LDG.128 gathers)
__global__ __launch_bounds__(256) void spmm_kernel(
    const int* __restrict__ rp, const int* __restrict__ ci,
    const float* __restrict__ deg, float* __restrict__ out, int n)
{
    const int node = (blockIdx.x * 256 + threadIdx.x) >> 5;
    if (node >= n) return;
    const int lane = threadIdx.x & 31;
    const int g = lane >> 3;
    const int q = lane & 7;

    const int start = rp[node];
    const int end   = rp[node + 1];
    const int m_all = end - start;

    const float4* Xp4 = reinterpret_cast<const float4*>(g_Xp);

    float4 a0 = make_float4(0.f, 0.f, 0.f, 0.f);
    float4 a1 = make_float4(0.f, 0.f, 0.f, 0.f);

    if (m_all == 16) {
        int   c = 0; float d = 0.f;
        if (lane < 16) { c = ci[start + lane]; d = deg[start + lane]; }
        #pragma unroll
        for (int t = 0; t < 4; ++t) {
            const int   cg = __shfl_sync(0xffffffffu, c, t * 4 + g);
            const float dg = __shfl_sync(0xffffffffu, d, t * 4 + g);
            const float4 v = __ldg(&Xp4[(size_t)cg * 8 + q]);
            float4& a = (t & 1) ? a1 : a0;
            a.x = fmaf(dg, v.x, a.x);
            a.y = fmaf(dg, v.y, a.y);
            a.z = fmaf(dg, v.z, a.z);
            a.w = fmaf(dg, v.w, a.w);
        }
    } else {
        for (int s = start; s < end; s += 32) {
            const int m = min(32, end - s);
            int   c = 0; float d = 0.f;
            if (lane < m) { c = ci[s + lane]; d = deg[s + lane]; }
            const int tmax = (m + 3) >> 2;
            for (int t = 0; t < tmax; ++t) {
                const int   idx = t * 4 + g;
                const int   cg = __shfl_sync(0xffffffffu, c, idx);
                const float dg = __shfl_sync(0xffffffffu, d, idx);
                if (idx < m) {
                    const float4 v = __ldg(&Xp4[(size_t)cg * 8 + q]);
                    a0.x = fmaf(dg, v.x, a0.x);
                    a0.y = fmaf(dg, v.y, a0.y);
                    a0.z = fmaf(dg, v.z, a0.z);
                    a0.w = fmaf(dg, v.w, a0.w);
                }
            }
        }
    }

    a0.x += a1.x; a0.y += a1.y; a0.z += a1.z; a0.w += a1.w;

    #pragma unroll
    for (int off = 8; off <= 16; off <<= 1) {
        a0.x += __shfl_xor_sync(0xffffffffu, a0.x, off);
        a0.y += __shfl_xor_sync(0xffffffffu, a0.y, off);
        a0.z += __shfl_xor_sync(0xffffffffu, a0.z, off);
        a0.w += __shfl_xor_sync(0xffffffffu, a0.w, off);
    }

    if (lane < 8)
        reinterpret_cast<float4*>(out + (size_t)node * F_OUT)[q] = a0;
}

// ---------------- launch -----------------------------------------------
extern "C" void kernel_launch(void* const* d_in, const int* in_sizes, int n_in,
                              void* d_out, int out_size)
{
    const float* X   = (const float*)d_in[0];   // [N,128]
    const float* W   = (const float*)d_in[1];   // [128,32]
    const float* b   = (const float*)d_in[2];   // [32]
    const int*   rp  = (const int*)  d_in[3];   // [N+1]
    const int*   ci  = (const int*)  d_in[4];   // [E]
    const float* deg = (const float*)d_in[5];   // [E]
    float* out = (float*)d_out;                 // [N,32]

    const int n = in_sizes[0] / F_IN;

    gemm_mma_kernel<<<(n + 127) / 128, 256>>>(X, W, b, n);
    spmm_kernel<<<(n + 7) / 8, 256>>>(rp, ci, deg, out, n);
}

// round 7
// speedup vs baseline: 2.1987x; 1.0760x over previous
#include <cuda_runtime.h>
#include <cuda_bf16.h>
#include <cstdint>

// Problem constants (GCNConv_68771016344004): N=100000, F_IN=128, F_OUT=32, E=N*16
#define F_IN   128
#define F_OUT  32
#define MAX_N  100000

// Scratch for Xp = X*W + b  (12.8 MB) — __device__ global per allocation rules.
__device__ float g_Xp[MAX_N * F_OUT];

// ---------------- helpers ----------------
__device__ __forceinline__ uint32_t pack_bf16x2(float a, float b) {
    __nv_bfloat162 h = __floats2bfloat162_rn(a, b);
    return *reinterpret_cast<uint32_t*>(&h);
}
__device__ __forceinline__ void ldmatrix_x4(uint32_t r[4], uint32_t addr) {
    asm volatile("ldmatrix.sync.aligned.m8n8.x4.shared.b16 {%0,%1,%2,%3}, [%4];"
                 : "=r"(r[0]), "=r"(r[1]), "=r"(r[2]), "=r"(r[3]) : "r"(addr));
}
__device__ __forceinline__ void ldmatrix_x4_trans(uint32_t r[4], uint32_t addr) {
    asm volatile("ldmatrix.sync.aligned.m8n8.x4.trans.shared.b16 {%0,%1,%2,%3}, [%4];"
                 : "=r"(r[0]), "=r"(r[1]), "=r"(r[2]), "=r"(r[3]) : "r"(addr));
}
__device__ __forceinline__ void mma_bf16(float c[4], const uint32_t a[4],
                                         uint32_t b0, uint32_t b1) {
    asm volatile(
        "mma.sync.aligned.m16n8k16.row.col.f32.bf16.bf16.f32 "
        "{%0,%1,%2,%3}, {%4,%5,%6,%7}, {%8,%9}, {%0,%1,%2,%3};"
        : "+f"(c[0]), "+f"(c[1]), "+f"(c[2]), "+f"(c[3])
        : "r"(a[0]), "r"(a[1]), "r"(a[2]), "r"(a[3]), "r"(b0), "r"(b1));
}

// ---------------- Kernel 1: Xp = X @ W + b  (bf16-split tensor-core) ----
// CTA: 256 threads (8 warps), tile = 128 rows, K in 2 halves of 64.
//   out = Xhi*Whi + Xhi*Wlo + Xlo*Whi   (lo*lo dropped, ~2^-18 rel)
// Half-1 global loads are issued BEFORE the half-0 MMA phase so DRAM latency
// overlaps tensor work (single-buffered smem, registers double-buffer).
#define APAD 72
#define BPAD 40

__global__ __launch_bounds__(256) void gemm_mma_kernel(
    const float* __restrict__ X, const float* __restrict__ W,
    const float* __restrict__ b, int n)
{
    __shared__ __align__(16) __nv_bfloat16 Ahi[128][APAD];
    __shared__ __align__(16) __nv_bfloat16 Alo[128][APAD];
    __shared__ __align__(16) __nv_bfloat16 Bhi[64][BPAD];
    __shared__ __align__(16) __nv_bfloat16 Blo[64][BPAD];

    const int tid  = threadIdx.x;
    const int lane = tid & 31;
    const int w    = tid >> 5;              // warp 0..7, owns rows [16w,16w+16)
    const int row0 = blockIdx.x * 128;

    float acc[4][4];
    #pragma unroll
    for (int nb = 0; nb < 4; nb++)
        #pragma unroll
        for (int j = 0; j < 4; j++) acc[nb][j] = 0.f;

    // per-thread load slots: A = 8 float4 (r = idx>>4, q = idx&15), B = 2 float4
    auto load_half = [&](int kh, float4 xa[8], float4 wb[2]) {
        #pragma unroll
        for (int i = 0; i < 8; i++) {
            const int idx = tid + 256 * i;
            const int r   = idx >> 4;
            const int q   = idx & 15;
            xa[i] = make_float4(0.f, 0.f, 0.f, 0.f);
            if (row0 + r < n)
                xa[i] = __ldg(reinterpret_cast<const float4*>(
                            X + (size_t)(row0 + r) * F_IN + kh * 64) + q);
        }
        #pragma unroll
        for (int i = 0; i < 2; i++) {
            const int idx = tid + 256 * i;
            const int r   = idx >> 3;
            const int q   = idx & 7;
            wb[i] = __ldg(reinterpret_cast<const float4*>(
                        W + (size_t)(kh * 64 + r) * F_OUT) + q);
        }
    };

    auto split_store = [&](const float4 xa[8], const float4 wb[2]) {
        #pragma unroll
        for (int i = 0; i < 8; i++) {
            const int idx = tid + 256 * i;
            const int r   = idx >> 4;
            const int q   = idx & 15;
            const float4 v = xa[i];
            float hx = __bfloat162float(__float2bfloat16_rn(v.x));
            float hy = __bfloat162float(__float2bfloat16_rn(v.y));
            float hz = __bfloat162float(__float2bfloat16_rn(v.z));
            float hw = __bfloat162float(__float2bfloat16_rn(v.w));
            *reinterpret_cast<uint2*>(&Ahi[r][q * 4]) =
                make_uint2(pack_bf16x2(hx, hy), pack_bf16x2(hz, hw));
            *reinterpret_cast<uint2*>(&Alo[r][q * 4]) =
                make_uint2(pack_bf16x2(v.x - hx, v.y - hy),
                           pack_bf16x2(v.z - hz, v.w - hw));
        }
        #pragma unroll
        for (int i = 0; i < 2; i++) {
            const int idx = tid + 256 * i;
            const int r   = idx >> 3;
            const int q   = idx & 7;
            const float4 v = wb[i];
            float hx = __bfloat162float(__float2bfloat16_rn(v.x));
            float hy = __bfloat162float(__float2bfloat16_rn(v.y));
            float hz = __bfloat162float(__float2bfloat16_rn(v.z));
            float hw = __bfloat162float(__float2bfloat16_rn(v.w));
            *reinterpret_cast<uint2*>(&Bhi[r][q * 4]) =
                make_uint2(pack_bf16x2(hx, hy), pack_bf16x2(hz, hw));
            *reinterpret_cast<uint2*>(&Blo[r][q * 4]) =
                make_uint2(pack_bf16x2(v.x - hx, v.y - hy),
                           pack_bf16x2(v.z - hz, v.w - hw));
        }
    };

    auto mma_half = [&]() {
        #pragma unroll
        for (int kc = 0; kc < 4; kc++) {
            uint32_t ahi[4], alo[4];
            {
                const int ar = 16 * w + (lane & 15);
                const int ac = kc * 16 + (lane >> 4) * 8;
                ldmatrix_x4(ahi, (uint32_t)__cvta_generic_to_shared(&Ahi[ar][ac]));
                ldmatrix_x4(alo, (uint32_t)__cvta_generic_to_shared(&Alo[ar][ac]));
            }
            uint32_t bhi[8], blo[8];
            {
                const int br = kc * 16 + (lane & 15);
                const int bc0 = (lane >> 4) * 8;
                ldmatrix_x4_trans(bhi,     (uint32_t)__cvta_generic_to_shared(&Bhi[br][bc0]));
                ldmatrix_x4_trans(bhi + 4, (uint32_t)__cvta_generic_to_shared(&Bhi[br][16 + bc0]));
                ldmatrix_x4_trans(blo,     (uint32_t)__cvta_generic_to_shared(&Blo[br][bc0]));
                ldmatrix_x4_trans(blo + 4, (uint32_t)__cvta_generic_to_shared(&Blo[br][16 + bc0]));
            }
            #pragma unroll
            for (int nb = 0; nb < 4; nb++) {
                const int o = (nb >> 1) * 4 + (nb & 1) * 2;
                mma_bf16(acc[nb], ahi, bhi[o], bhi[o + 1]);
                mma_bf16(acc[nb], ahi, blo[o], blo[o + 1]);
                mma_bf16(acc[nb], alo, bhi[o], bhi[o + 1]);
            }
        }
    };

    float4 xa0[8], wb0[2], xa1[8], wb1[2];
    load_half(0, xa0, wb0);
    split_store(xa0, wb0);
    load_half(1, xa1, wb1);      // DRAM latency overlaps half-0 MMA below
    __syncthreads();
    mma_half();
    __syncthreads();
    split_store(xa1, wb1);
    __syncthreads();
    mma_half();

    // epilogue: + bias, store fp32 rows of Xp
    const int r0 = row0 + 16 * w + (lane >> 2);
    const int c0 = (lane & 3) * 2;
    #pragma unroll
    for (int nb = 0; nb < 4; nb++) {
        const int col = nb * 8 + c0;
        const float2 bv = __ldg(reinterpret_cast<const float2*>(b + col));
        if (r0 < n)
            *reinterpret_cast<float2*>(g_Xp + (size_t)r0 * F_OUT + col) =
                make_float2(acc[nb][0] + bv.x, acc[nb][1] + bv.y);
        if (r0 + 8 < n)
            *reinterpret_cast<float2*>(g_Xp + (size_t)(r0 + 8) * F_OUT + col) =
                make_float2(acc[nb][2] + bv.x, acc[nb][3] + bv.y);
    }
}

// ---------------- Kernel 2: out[i] = sum_e deg[e] * Xp[col[e]] ----------
// Warp per node, lanes (g=lane>>3, q=lane&7). v3: NO broadcast shuffles on
// the fast path — each lane loads ci/deg directly (8-lane sector broadcast,
// L1-hit). All 8 index/value chains + 4 gather chains are independent, so
// they pipeline from cycle 0. 4 independent accumulators, then 2-stage
// shfl_xor combine and one STG.128 per 8 lanes.
__global__ __launch_bounds__(256) void spmm_kernel(
    const int* __restrict__ rp, const int* __restrict__ ci,
    const float* __restrict__ deg, float* __restrict__ out, int n)
{
    const int node = (blockIdx.x * 256 + threadIdx.x) >> 5;
    if (node >= n) return;
    const int lane = threadIdx.x & 31;
    const int g = lane >> 3;
    const int q = lane & 7;

    const int start = rp[node];
    const int end   = rp[node + 1];
    const int m_all = end - start;

    const float4* Xp4 = reinterpret_cast<const float4*>(g_Xp);

    float4 a0 = make_float4(0.f, 0.f, 0.f, 0.f);
    float4 a1 = make_float4(0.f, 0.f, 0.f, 0.f);

    if (m_all == 16) {
        const int e = start + g;
        // 8 independent index/weight loads (no shfl, no serialization)
        const int   c0 = __ldg(ci + e);        const float d0 = __ldg(deg + e);
        const int   c1 = __ldg(ci + e + 4);    const float d1 = __ldg(deg + e + 4);
        const int   c2 = __ldg(ci + e + 8);    const float d2 = __ldg(deg + e + 8);
        const int   c3 = __ldg(ci + e + 12);   const float d3 = __ldg(deg + e + 12);

        const float4 v0 = __ldg(&Xp4[(size_t)c0 * 8 + q]);
        const float4 v1 = __ldg(&Xp4[(size_t)c1 * 8 + q]);
        const float4 v2 = __ldg(&Xp4[(size_t)c2 * 8 + q]);
        const float4 v3 = __ldg(&Xp4[(size_t)c3 * 8 + q]);

        float4 b0, b1_;
        b0.x  = d0 * v0.x;  b0.y  = d0 * v0.y;  b0.z  = d0 * v0.z;  b0.w  = d0 * v0.w;
        b1_.x = d1 * v1.x;  b1_.y = d1 * v1.y;  b1_.z = d1 * v1.z;  b1_.w = d1 * v1.w;
        b0.x  = fmaf(d2, v2.x, b0.x);  b0.y  = fmaf(d2, v2.y, b0.y);
        b0.z  = fmaf(d2, v2.z, b0.z);  b0.w  = fmaf(d2, v2.w, b0.w);
        b1_.x = fmaf(d3, v3.x, b1_.x); b1_.y = fmaf(d3, v3.y, b1_.y);
        b1_.z = fmaf(d3, v3.z, b1_.z); b1_.w = fmaf(d3, v3.w, b1_.w);
        a0 = b0; a1 = b1_;
    } else {
        // Generic path: any degree (shfl broadcast, as before).
        for (int s = start; s < end; s += 32) {
            const int m = min(32, end - s);
            int   c = 0; float d = 0.f;
            if (lane < m) { c = ci[s + lane]; d = deg[s + lane]; }
            const int tmax = (m + 3) >> 2;
            for (int t = 0; t < tmax; ++t) {
                const int   idx = t * 4 + g;
                const int   cg = __shfl_sync(0xffffffffu, c, idx);
                const float dg = __shfl_sync(0xffffffffu, d, idx);
                if (idx < m) {
                    const float4 v = __ldg(&Xp4[(size_t)cg * 8 + q]);
                    a0.x = fmaf(dg, v.x, a0.x);
                    a0.y = fmaf(dg, v.y, a0.y);
                    a0.z = fmaf(dg, v.z, a0.z);
                    a0.w = fmaf(dg, v.w, a0.w);
                }
            }
        }
    }

    a0.x += a1.x; a0.y += a1.y; a0.z += a1.z; a0.w += a1.w;

    // Reduce across the 4 groups (lanes xor 8, xor 16)
    #pragma unroll
    for (int off = 8; off <= 16; off <<= 1) {
        a0.x += __shfl_xor_sync(0xffffffffu, a0.x, off);
        a0.y += __shfl_xor_sync(0xffffffffu, a0.y, off);
        a0.z += __shfl_xor_sync(0xffffffffu, a0.z, off);
        a0.w += __shfl_xor_sync(0xffffffffu, a0.w, off);
    }

    if (lane < 8)
        reinterpret_cast<float4*>(out + (size_t)node * F_OUT)[q] = a0;
}

// ---------------- launch -----------------------------------------------
extern "C" void kernel_launch(void* const* d_in, const int* in_sizes, int n_in,
                              void* d_out, int out_size)
{
    const float* X   = (const float*)d_in[0];   // [N,128]
    const float* W   = (const float*)d_in[1];   // [128,32]
    const float* b   = (const float*)d_in[2];   // [32]
    const int*   rp  = (const int*)  d_in[3];   // [N+1]
    const int*   ci  = (const int*)  d_in[4];   // [E]
    const float* deg = (const float*)d_in[5];   // [E]
    float* out = (float*)d_out;                 // [N,32]

    const int n = in_sizes[0] / F_IN;

    gemm_mma_kernel<<<(n + 127) / 128, 256>>>(X, W, b, n);
    spmm_kernel<<<(n + 7) / 8, 256>>>(rp, ci, deg, out, n);
}

// round 8
// speedup vs baseline: 2.4996x; 1.1368x over previous
#include <cuda_runtime.h>
#include <cuda_bf16.h>
#include <cstdint>

// Problem constants (GCNConv_68771016344004): N=100000, F_IN=128, F_OUT=32, E=N*16
#define F_IN   128
#define F_OUT  32
#define MAX_N  100000

// Scratch for Xp = X*W + b  (12.8 MB) — __device__ global per allocation rules.
__device__ float g_Xp[MAX_N * F_OUT];

// ---------------- helpers ----------------
__device__ __forceinline__ uint32_t pack_bf16x2(float a, float b) {
    __nv_bfloat162 h = __floats2bfloat162_rn(a, b);
    return *reinterpret_cast<uint32_t*>(&h);
}
__device__ __forceinline__ void ldmatrix_x4(uint32_t r[4], uint32_t addr) {
    asm volatile("ldmatrix.sync.aligned.m8n8.x4.shared.b16 {%0,%1,%2,%3}, [%4];"
                 : "=r"(r[0]), "=r"(r[1]), "=r"(r[2]), "=r"(r[3]) : "r"(addr));
}
__device__ __forceinline__ void ldmatrix_x4_trans(uint32_t r[4], uint32_t addr) {
    asm volatile("ldmatrix.sync.aligned.m8n8.x4.trans.shared.b16 {%0,%1,%2,%3}, [%4];"
                 : "=r"(r[0]), "=r"(r[1]), "=r"(r[2]), "=r"(r[3]) : "r"(addr));
}
__device__ __forceinline__ void mma_bf16(float c[4], const uint32_t a[4],
                                         uint32_t b0, uint32_t b1) {
    asm volatile(
        "mma.sync.aligned.m16n8k16.row.col.f32.bf16.bf16.f32 "
        "{%0,%1,%2,%3}, {%4,%5,%6,%7}, {%8,%9}, {%0,%1,%2,%3};"
        : "+f"(c[0]), "+f"(c[1]), "+f"(c[2]), "+f"(c[3])
        : "r"(a[0]), "r"(a[1]), "r"(a[2]), "r"(a[3]), "r"(b0), "r"(b1));
}

// ---------------- Kernel 1: Xp = X @ W + b  (bf16-split tensor-core) ----
// (unchanged from R6 — register-prefetched half-1, split-bf16 3-term MMA)
#define APAD 72
#define BPAD 40

__global__ __launch_bounds__(256) void gemm_mma_kernel(
    const float* __restrict__ X, const float* __restrict__ W,
    const float* __restrict__ b, int n)
{
    __shared__ __align__(16) __nv_bfloat16 Ahi[128][APAD];
    __shared__ __align__(16) __nv_bfloat16 Alo[128][APAD];
    __shared__ __align__(16) __nv_bfloat16 Bhi[64][BPAD];
    __shared__ __align__(16) __nv_bfloat16 Blo[64][BPAD];

    const int tid  = threadIdx.x;
    const int lane = tid & 31;
    const int w    = tid >> 5;
    const int row0 = blockIdx.x * 128;

    float acc[4][4];
    #pragma unroll
    for (int nb = 0; nb < 4; nb++)
        #pragma unroll
        for (int j = 0; j < 4; j++) acc[nb][j] = 0.f;

    auto load_half = [&](int kh, float4 xa[8], float4 wb[2]) {
        #pragma unroll
        for (int i = 0; i < 8; i++) {
            const int idx = tid + 256 * i;
            const int r   = idx >> 4;
            const int q   = idx & 15;
            xa[i] = make_float4(0.f, 0.f, 0.f, 0.f);
            if (row0 + r < n)
                xa[i] = __ldg(reinterpret_cast<const float4*>(
                            X + (size_t)(row0 + r) * F_IN + kh * 64) + q);
        }
        #pragma unroll
        for (int i = 0; i < 2; i++) {
            const int idx = tid + 256 * i;
            const int r   = idx >> 3;
            const int q   = idx & 7;
            wb[i] = __ldg(reinterpret_cast<const float4*>(
                        W + (size_t)(kh * 64 + r) * F_OUT) + q);
        }
    };

    auto split_store = [&](const float4 xa[8], const float4 wb[2]) {
        #pragma unroll
        for (int i = 0; i < 8; i++) {
            const int idx = tid + 256 * i;
            const int r   = idx >> 4;
            const int q   = idx & 15;
            const float4 v = xa[i];
            float hx = __bfloat162float(__float2bfloat16_rn(v.x));
            float hy = __bfloat162float(__float2bfloat16_rn(v.y));
            float hz = __bfloat162float(__float2bfloat16_rn(v.z));
            float hw = __bfloat162float(__float2bfloat16_rn(v.w));
            *reinterpret_cast<uint2*>(&Ahi[r][q * 4]) =
                make_uint2(pack_bf16x2(hx, hy), pack_bf16x2(hz, hw));
            *reinterpret_cast<uint2*>(&Alo[r][q * 4]) =
                make_uint2(pack_bf16x2(v.x - hx, v.y - hy),
                           pack_bf16x2(v.z - hz, v.w - hw));
        }
        #pragma unroll
        for (int i = 0; i < 2; i++) {
            const int idx = tid + 256 * i;
            const int r   = idx >> 3;
            const int q   = idx & 7;
            const float4 v = wb[i];
            float hx = __bfloat162float(__float2bfloat16_rn(v.x));
            float hy = __bfloat162float(__float2bfloat16_rn(v.y));
            float hz = __bfloat162float(__float2bfloat16_rn(v.z));
            float hw = __bfloat162float(__float2bfloat16_rn(v.w));
            *reinterpret_cast<uint2*>(&Bhi[r][q * 4]) =
                make_uint2(pack_bf16x2(hx, hy), pack_bf16x2(hz, hw));
            *reinterpret_cast<uint2*>(&Blo[r][q * 4]) =
                make_uint2(pack_bf16x2(v.x - hx, v.y - hy),
                           pack_bf16x2(v.z - hz, v.w - hw));
        }
    };

    auto mma_half = [&]() {
        #pragma unroll
        for (int kc = 0; kc < 4; kc++) {
            uint32_t ahi[4], alo[4];
            {
                const int ar = 16 * w + (lane & 15);
                const int ac = kc * 16 + (lane >> 4) * 8;
                ldmatrix_x4(ahi, (uint32_t)__cvta_generic_to_shared(&Ahi[ar][ac]));
                ldmatrix_x4(alo, (uint32_t)__cvta_generic_to_shared(&Alo[ar][ac]));
            }
            uint32_t bhi[8], blo[8];
            {
                const int br = kc * 16 + (lane & 15);
                const int bc0 = (lane >> 4) * 8;
                ldmatrix_x4_trans(bhi,     (uint32_t)__cvta_generic_to_shared(&Bhi[br][bc0]));
                ldmatrix_x4_trans(bhi + 4, (uint32_t)__cvta_generic_to_shared(&Bhi[br][16 + bc0]));
                ldmatrix_x4_trans(blo,     (uint32_t)__cvta_generic_to_shared(&Blo[br][bc0]));
                ldmatrix_x4_trans(blo + 4, (uint32_t)__cvta_generic_to_shared(&Blo[br][16 + bc0]));
            }
            #pragma unroll
            for (int nb = 0; nb < 4; nb++) {
                const int o = (nb >> 1) * 4 + (nb & 1) * 2;
                mma_bf16(acc[nb], ahi, bhi[o], bhi[o + 1]);
                mma_bf16(acc[nb], ahi, blo[o], blo[o + 1]);
                mma_bf16(acc[nb], alo, bhi[o], bhi[o + 1]);
            }
        }
    };

    float4 xa0[8], wb0[2], xa1[8], wb1[2];
    load_half(0, xa0, wb0);
    split_store(xa0, wb0);
    load_half(1, xa1, wb1);      // DRAM latency overlaps half-0 MMA below
    __syncthreads();
    mma_half();
    __syncthreads();
    split_store(xa1, wb1);
    __syncthreads();
    mma_half();

    const int r0 = row0 + 16 * w + (lane >> 2);
    const int c0 = (lane & 3) * 2;
    #pragma unroll
    for (int nb = 0; nb < 4; nb++) {
        const int col = nb * 8 + c0;
        const float2 bv = __ldg(reinterpret_cast<const float2*>(b + col));
        if (r0 < n)
            *reinterpret_cast<float2*>(g_Xp + (size_t)r0 * F_OUT + col) =
                make_float2(acc[nb][0] + bv.x, acc[nb][1] + bv.y);
        if (r0 + 8 < n)
            *reinterpret_cast<float2*>(g_Xp + (size_t)(r0 + 8) * F_OUT + col) =
                make_float2(acc[nb][2] + bv.x, acc[nb][3] + bv.y);
    }
}

// ---------------- Kernel 2: out[i] = sum_e deg[e] * Xp[col[e]] ----------
// v4: 2 consecutive nodes per warp; speculative ci/deg loads at node*16
// issued IN PARALLEL with the rp loads (verified after; generic fallback on
// mismatch). 8 gather chains in flight per warp. Final store: one STG.128
// with 16 active lanes covering both nodes' contiguous 256B.
__device__ __forceinline__ float4 spmm_node_generic(
    const int* __restrict__ ci, const float* __restrict__ deg,
    const float4* __restrict__ Xp4, int start, int end, int g, int q)
{
    float4 a = make_float4(0.f, 0.f, 0.f, 0.f);
    for (int s = start; s < end; s += 4) {
        const int e = s + g;
        if (e < end) {
            const int   c = __ldg(ci + e);
            const float d = __ldg(deg + e);
            const float4 v = __ldg(&Xp4[(size_t)c * 8 + q]);
            a.x = fmaf(d, v.x, a.x);
            a.y = fmaf(d, v.y, a.y);
            a.z = fmaf(d, v.z, a.z);
            a.w = fmaf(d, v.w, a.w);
        }
    }
    return a;
}

__global__ __launch_bounds__(256) void spmm_kernel(
    const int* __restrict__ rp, const int* __restrict__ ci,
    const float* __restrict__ deg, float* __restrict__ out, int n, int E)
{
    const int warp  = (blockIdx.x * 256 + threadIdx.x) >> 5;
    const int node0 = warp * 2;
    if (node0 >= n) return;
    const int node1 = node0 + 1;
    const bool has1 = node1 < n;

    const int lane = threadIdx.x & 31;
    const int g = lane >> 3;
    const int q = lane & 7;

    const float4* Xp4 = reinterpret_cast<const float4*>(g_Xp);

    // rp loads (chain A) and speculative index loads (chain B) — independent.
    const int s0 = node0 * 16;
    const int s1 = node1 * 16;
    const bool spec_ok_bounds = (s1 + 16 <= E) || (!has1 && s0 + 16 <= E);

    const int r0 = __ldg(rp + node0);
    const int r1 = __ldg(rp + node0 + 1);
    const int r2 = has1 ? __ldg(rp + node0 + 2) : r1;

    float4 A = make_float4(0.f, 0.f, 0.f, 0.f);
    float4 B = make_float4(0.f, 0.f, 0.f, 0.f);

    if (spec_ok_bounds) {
        const int e0 = s0 + g;
        const int e1 = s1 + g;
        // 16 independent index/weight loads
        const int   c00 = __ldg(ci + e0);        const float d00 = __ldg(deg + e0);
        const int   c01 = __ldg(ci + e0 + 4);    const float d01 = __ldg(deg + e0 + 4);
        const int   c02 = __ldg(ci + e0 + 8);    const float d02 = __ldg(deg + e0 + 8);
        const int   c03 = __ldg(ci + e0 + 12);   const float d03 = __ldg(deg + e0 + 12);
        const int   c10 = __ldg(ci + e1);        const float d10 = __ldg(deg + e1);
        const int   c11 = __ldg(ci + e1 + 4);    const float d11 = __ldg(deg + e1 + 4);
        const int   c12 = __ldg(ci + e1 + 8);    const float d12 = __ldg(deg + e1 + 8);
        const int   c13 = __ldg(ci + e1 + 12);   const float d13 = __ldg(deg + e1 + 12);

        // 8 gather chains in flight
        const float4 v00 = __ldg(&Xp4[(size_t)c00 * 8 + q]);
        const float4 v01 = __ldg(&Xp4[(size_t)c01 * 8 + q]);
        const float4 v02 = __ldg(&Xp4[(size_t)c02 * 8 + q]);
        const float4 v03 = __ldg(&Xp4[(size_t)c03 * 8 + q]);
        const float4 v10 = __ldg(&Xp4[(size_t)c10 * 8 + q]);
        const float4 v11 = __ldg(&Xp4[(size_t)c11 * 8 + q]);
        const float4 v12 = __ldg(&Xp4[(size_t)c12 * 8 + q]);
        const float4 v13 = __ldg(&Xp4[(size_t)c13 * 8 + q]);

        float4 p0, p1;
        p0.x = d00 * v00.x; p0.y = d00 * v00.y; p0.z = d00 * v00.z; p0.w = d00 * v00.w;
        p1.x = d01 * v01.x; p1.y = d01 * v01.y; p1.z = d01 * v01.z; p1.w = d01 * v01.w;
        p0.x = fmaf(d02, v02.x, p0.x); p0.y = fmaf(d02, v02.y, p0.y);
        p0.z = fmaf(d02, v02.z, p0.z); p0.w = fmaf(d02, v02.w, p0.w);
        p1.x = fmaf(d03, v03.x, p1.x); p1.y = fmaf(d03, v03.y, p1.y);
        p1.z = fmaf(d03, v03.z, p1.z); p1.w = fmaf(d03, v03.w, p1.w);
        A.x = p0.x + p1.x; A.y = p0.y + p1.y; A.z = p0.z + p1.z; A.w = p0.w + p1.w;

        float4 q0, q1;
        q0.x = d10 * v10.x; q0.y = d10 * v10.y; q0.z = d10 * v10.z; q0.w = d10 * v10.w;
        q1.x = d11 * v11.x; q1.y = d11 * v11.y; q1.z = d11 * v11.z; q1.w = d11 * v11.w;
        q0.x = fmaf(d12, v12.x, q0.x); q0.y = fmaf(d12, v12.y, q0.y);
        q0.z = fmaf(d12, v12.z, q0.z); q0.w = fmaf(d12, v12.w, q0.w);
        q1.x = fmaf(d13, v13.x, q1.x); q1.y = fmaf(d13, v13.y, q1.y);
        q1.z = fmaf(d13, v13.z, q1.z); q1.w = fmaf(d13, v13.w, q1.w);
        B.x = q0.x + q1.x; B.y = q0.y + q1.y; B.z = q0.z + q1.z; B.w = q0.w + q1.w;
    }

    // Verify speculation; rare fallback recomputes from true CSR bounds.
    const bool ok0 = spec_ok_bounds && (r0 == s0) && (r1 == s0 + 16);
    const bool ok1 = spec_ok_bounds && has1 && (r1 == s1) && (r2 == s1 + 16);
    if (!ok0) A = spmm_node_generic(ci, deg, Xp4, r0, r1, g, q);
    if (has1 && !ok1) B = spmm_node_generic(ci, deg, Xp4, r1, r2, g, q);

    // Reduce across the 4 groups for both nodes
    #pragma unroll
    for (int off = 8; off <= 16; off <<= 1) {
        A.x += __shfl_xor_sync(0xffffffffu, A.x, off);
        A.y += __shfl_xor_sync(0xffffffffu, A.y, off);
        A.z += __shfl_xor_sync(0xffffffffu, A.z, off);
        A.w += __shfl_xor_sync(0xffffffffu, A.w, off);
        B.x += __shfl_xor_sync(0xffffffffu, B.x, off);
        B.y += __shfl_xor_sync(0xffffffffu, B.y, off);
        B.z += __shfl_xor_sync(0xffffffffu, B.z, off);
        B.w += __shfl_xor_sync(0xffffffffu, B.w, off);
    }

    // One coalesced 256B store: lanes 0-7 node0 row, lanes 8-15 node1 row.
    const float4 sv = (lane < 8) ? A : B;
    if (lane < 16 && (lane < 8 || has1))
        reinterpret_cast<float4*>(out + (size_t)node0 * F_OUT)[lane] = sv;
}

// ---------------- launch -----------------------------------------------
extern "C" void kernel_launch(void* const* d_in, const int* in_sizes, int n_in,
                              void* d_out, int out_size)
{
    const float* X   = (const float*)d_in[0];   // [N,128]
    const float* W   = (const float*)d_in[1];   // [128,32]
    const float* b   = (const float*)d_in[2];   // [32]
    const int*   rp  = (const int*)  d_in[3];   // [N+1]
    const int*   ci  = (const int*)  d_in[4];   // [E]
    const float* deg = (const float*)d_in[5];   // [E]
    float* out = (float*)d_out;                 // [N,32]

    const int n = in_sizes[0] / F_IN;
    const int E = in_sizes[4];

    gemm_mma_kernel<<<(n + 127) / 128, 256>>>(X, W, b, n);
    spmm_kernel<<<(n + 15) / 16, 256>>>(rp, ci, deg, out, n, E);
}

// round 10
// speedup vs baseline: 2.6702x; 1.0683x over previous
#include <cuda_runtime.h>
#include <cuda_bf16.h>
#include <cstdint>

// Problem constants (GCNConv_68771016344004): N=100000, F_IN=128, F_OUT=32, E=N*16
#define F_IN   128
#define F_OUT  32
#define MAX_N  100000

// Scratch for Xp = X*W + b  (12.8 MB) — __device__ global per allocation rules.
__device__ float g_Xp[MAX_N * F_OUT];

// ---------------- helpers ----------------
__device__ __forceinline__ uint32_t pack_bf16x2(float a, float b) {
    __nv_bfloat162 h = __floats2bfloat162_rn(a, b);
    return *reinterpret_cast<uint32_t*>(&h);
}
__device__ __forceinline__ void ldmatrix_x4(uint32_t r[4], uint32_t addr) {
    asm volatile("ldmatrix.sync.aligned.m8n8.x4.shared.b16 {%0,%1,%2,%3}, [%4];"
                 : "=r"(r[0]), "=r"(r[1]), "=r"(r[2]), "=r"(r[3]) : "r"(addr));
}
__device__ __forceinline__ void ldmatrix_x4_trans(uint32_t r[4], uint32_t addr) {
    asm volatile("ldmatrix.sync.aligned.m8n8.x4.trans.shared.b16 {%0,%1,%2,%3}, [%4];"
                 : "=r"(r[0]), "=r"(r[1]), "=r"(r[2]), "=r"(r[3]) : "r"(addr));
}
__device__ __forceinline__ void mma_bf16(float c[4], const uint32_t a[4],
                                         uint32_t b0, uint32_t b1) {
    asm volatile(
        "mma.sync.aligned.m16n8k16.row.col.f32.bf16.bf16.f32 "
        "{%0,%1,%2,%3}, {%4,%5,%6,%7}, {%8,%9}, {%0,%1,%2,%3};"
        : "+f"(c[0]), "+f"(c[1]), "+f"(c[2]), "+f"(c[3])
        : "r"(a[0]), "r"(a[1]), "r"(a[2]), "r"(a[3]), "r"(b0), "r"(b1));
}

// ---------------- Kernel 1: Xp = X @ W + b  (bf16-split tensor-core) ----
// (register-prefetched half-1, split-bf16 3-term MMA)
#define APAD 72
#define BPAD 40

__global__ __launch_bounds__(256) void gemm_mma_kernel(
    const float* __restrict__ X, const float* __restrict__ W,
    const float* __restrict__ b, int n)
{
    __shared__ __align__(16) __nv_bfloat16 Ahi[128][APAD];
    __shared__ __align__(16) __nv_bfloat16 Alo[128][APAD];
    __shared__ __align__(16) __nv_bfloat16 Bhi[64][BPAD];
    __shared__ __align__(16) __nv_bfloat16 Blo[64][BPAD];

    const int tid  = threadIdx.x;
    const int lane = tid & 31;
    const int w    = tid >> 5;
    const int row0 = blockIdx.x * 128;

    float acc[4][4];
    #pragma unroll
    for (int nb = 0; nb < 4; nb++)
        #pragma unroll
        for (int j = 0; j < 4; j++) acc[nb][j] = 0.f;

    auto load_half = [&](int kh, float4 xa[8], float4 wb[2]) {
        #pragma unroll
        for (int i = 0; i < 8; i++) {
            const int idx = tid + 256 * i;
            const int r   = idx >> 4;
            const int q   = idx & 15;
            xa[i] = make_float4(0.f, 0.f, 0.f, 0.f);
            if (row0 + r < n)
                xa[i] = __ldg(reinterpret_cast<const float4*>(
                            X + (size_t)(row0 + r) * F_IN + kh * 64) + q);
        }
        #pragma unroll
        for (int i = 0; i < 2; i++) {
            const int idx = tid + 256 * i;
            const int r   = idx >> 3;
            const int q   = idx & 7;
            wb[i] = __ldg(reinterpret_cast<const float4*>(
                        W + (size_t)(kh * 64 + r) * F_OUT) + q);
        }
    };

    auto split_store = [&](const float4 xa[8], const float4 wb[2]) {
        #pragma unroll
        for (int i = 0; i < 8; i++) {
            const int idx = tid + 256 * i;
            const int r   = idx >> 4;
            const int q   = idx & 15;
            const float4 v = xa[i];
            float hx = __bfloat162float(__float2bfloat16_rn(v.x));
            float hy = __bfloat162float(__float2bfloat16_rn(v.y));
            float hz = __bfloat162float(__float2bfloat16_rn(v.z));
            float hw = __bfloat162float(__float2bfloat16_rn(v.w));
            *reinterpret_cast<uint2*>(&Ahi[r][q * 4]) =
                make_uint2(pack_bf16x2(hx, hy), pack_bf16x2(hz, hw));
            *reinterpret_cast<uint2*>(&Alo[r][q * 4]) =
                make_uint2(pack_bf16x2(v.x - hx, v.y - hy),
                           pack_bf16x2(v.z - hz, v.w - hw));
        }
        #pragma unroll
        for (int i = 0; i < 2; i++) {
            const int idx = tid + 256 * i;
            const int r   = idx >> 3;
            const int q   = idx & 7;
            const float4 v = wb[i];
            float hx = __bfloat162float(__float2bfloat16_rn(v.x));
            float hy = __bfloat162float(__float2bfloat16_rn(v.y));
            float hz = __bfloat162float(__float2bfloat16_rn(v.z));
            float hw = __bfloat162float(__float2bfloat16_rn(v.w));
            *reinterpret_cast<uint2*>(&Bhi[r][q * 4]) =
                make_uint2(pack_bf16x2(hx, hy), pack_bf16x2(hz, hw));
            *reinterpret_cast<uint2*>(&Blo[r][q * 4]) =
                make_uint2(pack_bf16x2(v.x - hx, v.y - hy),
                           pack_bf16x2(v.z - hz, v.w - hw));
        }
    };

    auto mma_half = [&]() {
        #pragma unroll
        for (int kc = 0; kc < 4; kc++) {
            uint32_t ahi[4], alo[4];
            {
                const int ar = 16 * w + (lane & 15);
                const int ac = kc * 16 + (lane >> 4) * 8;
                ldmatrix_x4(ahi, (uint32_t)__cvta_generic_to_shared(&Ahi[ar][ac]));
                ldmatrix_x4(alo, (uint32_t)__cvta_generic_to_shared(&Alo[ar][ac]));
            }
            uint32_t bhi[8], blo[8];
            {
                const int br = kc * 16 + (lane & 15);
                const int bc0 = (lane >> 4) * 8;
                ldmatrix_x4_trans(bhi,     (uint32_t)__cvta_generic_to_shared(&Bhi[br][bc0]));
                ldmatrix_x4_trans(bhi + 4, (uint32_t)__cvta_generic_to_shared(&Bhi[br][16 + bc0]));
                ldmatrix_x4_trans(blo,     (uint32_t)__cvta_generic_to_shared(&Blo[br][bc0]));
                ldmatrix_x4_trans(blo + 4, (uint32_t)__cvta_generic_to_shared(&Blo[br][16 + bc0]));
            }
            #pragma unroll
            for (int nb = 0; nb < 4; nb++) {
                const int o = (nb >> 1) * 4 + (nb & 1) * 2;
                mma_bf16(acc[nb], ahi, bhi[o], bhi[o + 1]);
                mma_bf16(acc[nb], ahi, blo[o], blo[o + 1]);
                mma_bf16(acc[nb], alo, bhi[o], bhi[o + 1]);
            }
        }
    };

    float4 xa0[8], wb0[2], xa1[8], wb1[2];
    load_half(0, xa0, wb0);
    split_store(xa0, wb0);
    load_half(1, xa1, wb1);      // DRAM latency overlaps half-0 MMA below
    __syncthreads();
    mma_half();
    __syncthreads();
    split_store(xa1, wb1);
    __syncthreads();
    mma_half();

    const int r0 = row0 + 16 * w + (lane >> 2);
    const int c0 = (lane & 3) * 2;
    #pragma unroll
    for (int nb = 0; nb < 4; nb++) {
        const int col = nb * 8 + c0;
        const float2 bv = __ldg(reinterpret_cast<const float2*>(b + col));
        if (r0 < n)
            *reinterpret_cast<float2*>(g_Xp + (size_t)r0 * F_OUT + col) =
                make_float2(acc[nb][0] + bv.x, acc[nb][1] + bv.y);
        if (r0 + 8 < n)
            *reinterpret_cast<float2*>(g_Xp + (size_t)(r0 + 8) * F_OUT + col) =
                make_float2(acc[nb][2] + bv.x, acc[nb][3] + bv.y);
    }
}

// ---------------- Kernel 2: out[i] = sum_e deg[e] * Xp[col[e]] ----------
// v5: 4 nodes per warp; lane group g (8 lanes) OWNS node node0+g outright:
//   - ci/deg for the node's 16 edges loaded as 4x int4 + 4x float4 (16B
//     aligned on the speculative path, broadcast within the group)
//   - 16 gather chains in flight per warp (4 batches x 4)
//   - NO cross-group reduction shuffles
//   - store: 32 lanes x float4 = one coalesced 512B STG (4 consecutive rows)
// Speculative indexing at node*16 runs in parallel with the rp loads and is
// verified against rp; per-node generic fallback on mismatch.
__global__ __launch_bounds__(256) void spmm_kernel(
    const int* __restrict__ rp, const int* __restrict__ ci,
    const float* __restrict__ deg, float* __restrict__ out, int n, int E)
{
    const int warp  = (blockIdx.x * 256 + threadIdx.x) >> 5;
    const int node0 = warp * 4;
    if (node0 >= n) return;

    const int lane = threadIdx.x & 31;
    const int g = lane >> 3;          // group = node index within the quad
    const int q = lane & 7;           // float4 chunk within the node's row
    const int node = node0 + g;
    const bool active = node < n;

    const float4* Xp4 = reinterpret_cast<const float4*>(g_Xp);

    // Independent chains: rp verification loads + speculative index loads.
    const int s = node * 16;
    const bool spec_bounds = active && (s + 16 <= E);

    int r_lo = 0, r_hi = 0;
    if (active) { r_lo = __ldg(rp + node); r_hi = __ldg(rp + node + 1); }

    float4 a0 = make_float4(0.f, 0.f, 0.f, 0.f);
    float4 a1 = make_float4(0.f, 0.f, 0.f, 0.f);
    float4 a2 = make_float4(0.f, 0.f, 0.f, 0.f);
    float4 a3 = make_float4(0.f, 0.f, 0.f, 0.f);

    if (spec_bounds) {
        const int4*   ci4 = reinterpret_cast<const int4*>(ci + s);    // 16B aligned
        const float4* dg4 = reinterpret_cast<const float4*>(deg + s); // 16B aligned
        const int4   c0 = __ldg(ci4 + 0), c1 = __ldg(ci4 + 1),
                     c2 = __ldg(ci4 + 2), c3 = __ldg(ci4 + 3);
        const float4 d0 = __ldg(dg4 + 0), d1 = __ldg(dg4 + 1),
                     d2 = __ldg(dg4 + 2), d3 = __ldg(dg4 + 3);

        // 16 independent gathers (4 batches), 4 independent accumulators
        {
            const float4 v0 = __ldg(&Xp4[(size_t)c0.x * 8 + q]);
            const float4 v1 = __ldg(&Xp4[(size_t)c0.y * 8 + q]);
            const float4 v2 = __ldg(&Xp4[(size_t)c0.z * 8 + q]);
            const float4 v3 = __ldg(&Xp4[(size_t)c0.w * 8 + q]);
            a0.x = fmaf(d0.x, v0.x, a0.x); a0.y = fmaf(d0.x, v0.y, a0.y);
            a0.z = fmaf(d0.x, v0.z, a0.z); a0.w = fmaf(d0.x, v0.w, a0.w);
            a1.x = fmaf(d0.y, v1.x, a1.x); a1.y = fmaf(d0.y, v1.y, a1.y);
            a1.z = fmaf(d0.y, v1.z, a1.z); a1.w = fmaf(d0.y, v1.w, a1.w);
            a2.x = fmaf(d0.z, v2.x, a2.x); a2.y = fmaf(d0.z, v2.y, a2.y);
            a2.z = fmaf(d0.z, v2.z, a2.z); a2.w = fmaf(d0.z, v2.w, a2.w);
            a3.x = fmaf(d0.w, v3.x, a3.x); a3.y = fmaf(d0.w, v3.y, a3.y);
            a3.z = fmaf(d0.w, v3.z, a3.z); a3.w = fmaf(d0.w, v3.w, a3.w);
        }
        {
            const float4 v0 = __ldg(&Xp4[(size_t)c1.x * 8 + q]);
            const float4 v1 = __ldg(&Xp4[(size_t)c1.y * 8 + q]);
            const float4 v2 = __ldg(&Xp4[(size_t)c1.z * 8 + q]);
            const float4 v3 = __ldg(&Xp4[(size_t)c1.w * 8 + q]);
            a0.x = fmaf(d1.x, v0.x, a0.x); a0.y = fmaf(d1.x, v0.y, a0.y);
            a0.z = fmaf(d1.x, v0.z, a0.z); a0.w = fmaf(d1.x, v0.w, a0.w);
            a1.x = fmaf(d1.y, v1.x, a1.x); a1.y = fmaf(d1.y, v1.y, a1.y);
            a1.z = fmaf(d1.y, v1.z, a1.z); a1.w = fmaf(d1.y, v1.w, a1.w);
            a2.x = fmaf(d1.z, v2.x, a2.x); a2.y = fmaf(d1.z, v2.y, a2.y);
            a2.z = fmaf(d1.z, v2.z, a2.z); a2.w = fmaf(d1.z, v2.w, a2.w);
            a3.x = fmaf(d1.w, v3.x, a3.x); a3.y = fmaf(d1.w, v3.y, a3.y);
            a3.z = fmaf(d1.w, v3.z, a3.z); a3.w = fmaf(d1.w, v3.w, a3.w);
        }
        {
            const float4 v0 = __ldg(&Xp4[(size_t)c2.x * 8 + q]);
            const float4 v1 = __ldg(&Xp4[(size_t)c2.y * 8 + q]);
            const float4 v2 = __ldg(&Xp4[(size_t)c2.z * 8 + q]);
            const float4 v3 = __ldg(&Xp4[(size_t)c2.w * 8 + q]);
            a0.x = fmaf(d2.x, v0.x, a0.x); a0.y = fmaf(d2.x, v0.y, a0.y);
            a0.z = fmaf(d2.x, v0.z, a0.z); a0.w = fmaf(d2.x, v0.w, a0.w);
            a1.x = fmaf(d2.y, v1.x, a1.x); a1.y = fmaf(d2.y, v1.y, a1.y);
            a1.z = fmaf(d2.y, v1.z, a1.z); a1.w = fmaf(d2.y, v1.w, a1.w);
            a2.x = fmaf(d2.z, v2.x, a2.x); a2.y = fmaf(d2.z, v2.y, a2.y);
            a2.z = fmaf(d2.z, v2.z, a2.z); a2.w = fmaf(d2.z, v2.w, a2.w);
            a3.x = fmaf(d2.w, v3.x, a3.x); a3.y = fmaf(d2.w, v3.y, a3.y);
            a3.z = fmaf(d2.w, v3.z, a3.z); a3.w = fmaf(d2.w, v3.w, a3.w);
        }
        {
            const float4 v0 = __ldg(&Xp4[(size_t)c3.x * 8 + q]);
            const float4 v1 = __ldg(&Xp4[(size_t)c3.y * 8 + q]);
            const float4 v2 = __ldg(&Xp4[(size_t)c3.z * 8 + q]);
            const float4 v3 = __ldg(&Xp4[(size_t)c3.w * 8 + q]);
            a0.x = fmaf(d3.x, v0.x, a0.x); a0.y = fmaf(d3.x, v0.y, a0.y);
            a0.z = fmaf(d3.x, v0.z, a0.z); a0.w = fmaf(d3.x, v0.w, a0.w);
            a1.x = fmaf(d3.y, v1.x, a1.x); a1.y = fmaf(d3.y, v1.y, a1.y);
            a1.z = fmaf(d3.y, v1.z, a1.z); a1.w = fmaf(d3.y, v1.w, a1.w);
            a2.x = fmaf(d3.z, v2.x, a2.x); a2.y = fmaf(d3.z, v2.y, a2.y);
            a2.z = fmaf(d3.z, v2.z, a2.z); a2.w = fmaf(d3.z, v2.w, a2.w);
            a3.x = fmaf(d3.w, v3.x, a3.x); a3.y = fmaf(d3.w, v3.y, a3.y);
            a3.z = fmaf(d3.w, v3.z, a3.z); a3.w = fmaf(d3.w, v3.w, a3.w);
        }
    }

    // Verify speculation; per-node generic fallback (group-local, rare).
    const bool ok = spec_bounds && (r_lo == s) && (r_hi == s + 16);
    if (active && !ok) {
        a0 = a1 = a2 = a3 = make_float4(0.f, 0.f, 0.f, 0.f);
        for (int e = r_lo; e < r_hi; ++e) {
            const int   c = __ldg(ci + e);
            const float d = __ldg(deg + e);
            const float4 v = __ldg(&Xp4[(size_t)c * 8 + q]);
            a0.x = fmaf(d, v.x, a0.x); a0.y = fmaf(d, v.y, a0.y);
            a0.z = fmaf(d, v.z, a0.z); a0.w = fmaf(d, v.w, a0.w);
        }
    }

    float4 acc;
    acc.x = (a0.x + a1.x) + (a2.x + a3.x);
    acc.y = (a0.y + a1.y) + (a2.y + a3.y);
    acc.z = (a0.z + a1.z) + (a2.z + a3.z);
    acc.w = (a0.w + a1.w) + (a2.w + a3.w);

    // One coalesced 512B store: lane l writes float4 #l of the 4-row span.
    if (active)
        reinterpret_cast<float4*>(out)[(size_t)node0 * 8 + lane] = acc;
}

// ---------------- launch -----------------------------------------------
extern "C" void kernel_launch(void* const* d_in, const int* in_sizes, int n_in,
                              void* d_out, int out_size)
{
    const float* X   = (const float*)d_in[0];   // [N,128]
    const float* W   = (const float*)d_in[1];   // [128,32]
    const float* b   = (const float*)d_in[2];   // [32]
    const int*   rp  = (const int*)  d_in[3];   // [N+1]
    const int*   ci  = (const int*)  d_in[4];   // [E]
    const float* deg = (const float*)d_in[5];   // [E]
    float* out = (float*)d_out;                 // [N,32]

    const int n = in_sizes[0] / F_IN;
    const int E = in_sizes[4];

    gemm_mma_kernel<<<(n + 127) / 128, 256>>>(X, W, b, n);
    spmm_kernel<<<(n + 31) / 32, 256>>>(rp, ci, deg, out, n, E);
}